// round 6
// baseline (speedup 1.0000x reference)
#include <cuda_runtime.h>
#include <stdint.h>

// Problem constants
#define BZ   32
#define SEQ  2048
#define D    768
#define P    16
#define PLACEHOLDER_ID 1
#define ROWS (BZ * SEQ)          // 65536
#define D4   (D / 4)             // 192 float4 per row
#define ROWB 3072                // bytes per row

typedef unsigned long long ull;

// 32-byte gather load with L2 evict_last (sm_103 requires v4.b64 width for
// this hint). Keeps the 94MB emb table resident in the 126MB L2 across graph
// replays while the evict_first output stream sacrifices its own lines.
__device__ __forceinline__ void ldg_el32(const void* p, ull& x0, ull& x1, ull& x2, ull& x3) {
    asm volatile("ld.global.nc.L2::evict_last.v4.b64 {%0,%1,%2,%3}, [%4];"
                 : "=l"(x0), "=l"(x1), "=l"(x2), "=l"(x3) : "l"(p));
}

// 16-byte streaming store (evict_first)
__device__ __forceinline__ void stg_cs16(void* p, ull a, ull b) {
    asm volatile("st.global.cs.v2.b64 [%0], {%1,%2};" :: "l"(p), "l"(a), "l"(b) : "memory");
}

// ---------------------------------------------------------------------------
// Single fused kernel. 8192 blocks x 192 threads; block handles 8 consecutive
// rows of one batch row. Each thread owns one 32B chunk: chunk = t%96,
// sub = t/96; iteration i covers rows r0 + 2*i + sub (4 iters = 8 rows).
// ---------------------------------------------------------------------------
#define GTPB 192
#define RPB  8
#define GBLOCKS (ROWS / RPB)     // 8192

__global__ __launch_bounds__(GTPB)
void fused_prompt_embed_kernel(const int* __restrict__ input_ids,
                               const char* __restrict__ emb,
                               const float4* __restrict__ prompt,
                               char* __restrict__ out) {
    const int r0    = blockIdx.x * RPB;
    const int t     = threadIdx.x;
    const int chunk = t % 96;                // 32B chunk within row
    const int sub   = t / 96;                // 0 or 1
    const int batch = r0 >> 11;
    const int seq0  = r0 & (SEQ - 1);
    const int* rid  = input_ids + ((size_t)batch << 11);

    int ids[RPB];
#pragma unroll
    for (int i = 0; i < RPB; i++)
        ids[i] = __ldg(&rid[seq0 + i]);      // uniform per block (broadcast)

    // 4 independent 32B gathers (PLACEHOLDER_ID=1 is a valid emb row)
    ull v[4][4];
#pragma unroll
    for (int i = 0; i < 4; i++) {
        const void* src = emb + (size_t)ids[2 * i + sub] * ROWB + chunk * 32;
        ldg_el32(src, v[i][0], v[i][1], v[i][2], v[i][3]);
    }

    bool anyph = false;
#pragma unroll
    for (int i = 0; i < RPB; i++)
        anyph |= (ids[i] == PLACEHOLDER_ID);

#pragma unroll
    for (int i = 0; i < 4; i++) {
        const int j = 2 * i + sub;
        if (ids[j] != PLACEHOLDER_ID) {
            char* dst = out + (size_t)(r0 + j) * ROWB + chunk * 32;
            stg_cs16(dst,      v[i][0], v[i][1]);
            stg_cs16(dst + 16, v[i][2], v[i][3]);
        }
    }

    if (!anyph) return;                      // block-uniform branch (~494/8192)

    // ---- rare path: recover placeholder rank(s) for this block ----
    int cnt = 0;
    for (int q = t; q < seq0; q += GTPB)
        cnt += (__ldg(&rid[q]) == PLACEHOLDER_ID);

    __shared__ int s_sum;
    if (t == 0) s_sum = 0;
    __syncthreads();
#pragma unroll
    for (int off = 16; off > 0; off >>= 1)
        cnt += __shfl_down_sync(0xFFFFFFFFu, cnt, off);
    if ((t & 31) == 0) atomicAdd(&s_sum, cnt);
    __syncthreads();

#pragma unroll
    for (int i = 0; i < 4; i++) {
        const int j = 2 * i + sub;
        if (ids[j] == PLACEHOLDER_ID) {
            int rk = s_sum;                  // placeholders before seq0
            for (int q = 0; q < j; q++)
                rk += (ids[q] == PLACEHOLDER_ID);
            if (rk > P - 1) rk = P - 1;
            const float4* ps = prompt + (size_t)rk * D4 + chunk * 2;
            float4 a = __ldg(ps), b = __ldg(ps + 1);
            char* dst = out + (size_t)(r0 + j) * ROWB + chunk * 32;
            *(float4*)dst = a;
            *(float4*)(dst + 16) = b;
        }
    }
}

// ---------------------------------------------------------------------------
extern "C" void kernel_launch(void* const* d_in, const int* in_sizes, int n_in,
                              void* d_out, int out_size) {
    const int*    input_ids = (const int*)d_in[0];
    const char*   emb       = (const char*)d_in[1];
    const float4* prompt    = (const float4*)d_in[2];
    char*         out       = (char*)d_out;

    fused_prompt_embed_kernel<<<GBLOCKS, GTPB>>>(input_ids, emb, prompt, out);
}

// round 7
// speedup vs baseline: 1.1152x; 1.1152x over previous
#include <cuda_runtime.h>
#include <stdint.h>

// Problem constants
#define BZ   32
#define SEQ  2048
#define D    768
#define P    16
#define PLACEHOLDER_ID 1
#define ROWS (BZ * SEQ)          // 65536
#define D4   (D / 4)             // 192 float4 per row

// ---------------------------------------------------------------------------
// Single fused kernel (R4 champion shape). 8192 blocks x 192 threads; block
// handles 8 consecutive rows of one batch row.
// Hot path: 8 uniform id loads (2x LDG.128), 8 independent LDG.128 gathers
// (PLACEHOLDER_ID=1 is a valid emb row -> unconditional), 8 unconditional
// streaming stores. Placeholder rows (~494/8192 blocks) are then fixed up by
// the same threads, so the later prompt store is program-ordered after the
// bogus emb[1] store.
// ---------------------------------------------------------------------------
#define GTPB 192
#define RPB  8
#define GBLOCKS (ROWS / RPB)     // 8192

__global__ __launch_bounds__(GTPB)
void fused_prompt_embed_kernel(const int* __restrict__ input_ids,
                               const float4* __restrict__ emb,
                               const float4* __restrict__ prompt,
                               float4* __restrict__ out) {
    const int r0    = blockIdx.x * RPB;
    const int t     = threadIdx.x;
    const int batch = r0 >> 11;              // r0 / SEQ
    const int seq0  = r0 & (SEQ - 1);
    const int* rid  = input_ids + ((size_t)batch << 11);

    // 8 consecutive ids as two 16B loads (uniform per block)
    int4 ia = __ldg((const int4*)(rid + seq0));
    int4 ib = __ldg((const int4*)(rid + seq0) + 1);
    int ids[RPB] = { ia.x, ia.y, ia.z, ia.w, ib.x, ib.y, ib.z, ib.w };

    // 8 independent back-to-back gathers (MLP=8)
    float4 v[RPB];
#pragma unroll
    for (int i = 0; i < RPB; i++)
        v[i] = __ldg(emb + (size_t)ids[i] * D4 + t);

    // Unconditional coalesced streaming stores
#pragma unroll
    for (int i = 0; i < RPB; i++)
        __stcs(out + (size_t)(r0 + i) * D4 + t, v[i]);

    bool anyph = false;
#pragma unroll
    for (int i = 0; i < RPB; i++)
        anyph |= (ids[i] == PLACEHOLDER_ID);
    if (!anyph) return;                      // block-uniform branch

    // ---- rare path: recover placeholder rank(s), overwrite those rows ----
    int cnt = 0;
    for (int j = t; j < seq0; j += GTPB)
        cnt += (__ldg(&rid[j]) == PLACEHOLDER_ID);

    __shared__ int s_sum;
    if (t == 0) s_sum = 0;
    __syncthreads();
#pragma unroll
    for (int off = 16; off > 0; off >>= 1)
        cnt += __shfl_down_sync(0xFFFFFFFFu, cnt, off);
    if ((t & 31) == 0) atomicAdd(&s_sum, cnt);
    __syncthreads();

    int rank = s_sum;                        // placeholders before seq0
#pragma unroll
    for (int i = 0; i < RPB; i++) {
        if (ids[i] == PLACEHOLDER_ID) {
            int r = rank < (P - 1) ? rank : (P - 1);
            __stcs(out + (size_t)(r0 + i) * D4 + t, __ldg(&prompt[r * D4 + t]));
            rank++;
        }
    }
}

// ---------------------------------------------------------------------------
extern "C" void kernel_launch(void* const* d_in, const int* in_sizes, int n_in,
                              void* d_out, int out_size) {
    const int*    input_ids = (const int*)d_in[0];
    const float4* emb       = (const float4*)d_in[1];
    const float4* prompt    = (const float4*)d_in[2];
    float4*       out       = (float4*)d_out;

    fused_prompt_embed_kernel<<<GBLOCKS, GTPB>>>(input_ids, emb, prompt, out);
}

// round 8
// speedup vs baseline: 1.1159x; 1.0006x over previous
#include <cuda_runtime.h>
#include <stdint.h>

// Problem constants
#define BZ   32
#define SEQ  2048
#define D    768
#define P    16
#define PLACEHOLDER_ID 1
#define ROWS (BZ * SEQ)          // 65536
#define D4   (D / 4)             // 192 float4 per row

typedef unsigned long long ull;

// LDG.128 gather with a dynamic L2 cache policy (evict_last). Unlike the
// static ".L2::evict_last" qualifier (256-bit only on sm_103), the
// createpolicy + .L2::cache_hint form is width-unrestricted, so the access
// pattern stays byte-identical to the 53.3us champion.
__device__ __forceinline__ float4 ldg_policy(const float4* p, ull pol) {
    float4 v;
    asm volatile("ld.global.nc.L2::cache_hint.v4.f32 {%0,%1,%2,%3}, [%4], %5;"
                 : "=f"(v.x), "=f"(v.y), "=f"(v.z), "=f"(v.w)
                 : "l"(p), "l"(pol));
    return v;
}

// ---------------------------------------------------------------------------
// Single fused kernel (champion shape). 8192 blocks x 192 threads; block
// handles 8 consecutive rows of one batch row. Placeholder rows (~494/8192
// blocks) are overwritten afterwards by the same threads (program order).
// ---------------------------------------------------------------------------
#define GTPB 192
#define RPB  8
#define GBLOCKS (ROWS / RPB)     // 8192

__global__ __launch_bounds__(GTPB)
void fused_prompt_embed_kernel(const int* __restrict__ input_ids,
                               const float4* __restrict__ emb,
                               const float4* __restrict__ prompt,
                               float4* __restrict__ out) {
    const int r0    = blockIdx.x * RPB;
    const int t     = threadIdx.x;
    const int batch = r0 >> 11;              // r0 / SEQ
    const int seq0  = r0 & (SEQ - 1);
    const int* rid  = input_ids + ((size_t)batch << 11);

    // evict_last policy for the emb table (keep resident in L2 across replays)
    ull pol;
    asm volatile("createpolicy.fractional.L2::evict_last.b64 %0, 1.0;" : "=l"(pol));

    // 8 consecutive ids as two 16B loads (uniform per block)
    int4 ia = __ldg((const int4*)(rid + seq0));
    int4 ib = __ldg((const int4*)(rid + seq0) + 1);
    int ids[RPB] = { ia.x, ia.y, ia.z, ia.w, ib.x, ib.y, ib.z, ib.w };

    // 8 independent back-to-back LDG.128 gathers (MLP=8), evict_last policy
    float4 v[RPB];
#pragma unroll
    for (int i = 0; i < RPB; i++)
        v[i] = ldg_policy(emb + (size_t)ids[i] * D4 + t, pol);

    // Unconditional coalesced streaming stores (evict_first)
#pragma unroll
    for (int i = 0; i < RPB; i++)
        __stcs(out + (size_t)(r0 + i) * D4 + t, v[i]);

    bool anyph = false;
#pragma unroll
    for (int i = 0; i < RPB; i++)
        anyph |= (ids[i] == PLACEHOLDER_ID);
    if (!anyph) return;                      // block-uniform branch

    // ---- rare path: recover placeholder rank(s), overwrite those rows ----
    int cnt = 0;
    for (int j = t; j < seq0; j += GTPB)
        cnt += (__ldg(&rid[j]) == PLACEHOLDER_ID);

    __shared__ int s_sum;
    if (t == 0) s_sum = 0;
    __syncthreads();
#pragma unroll
    for (int off = 16; off > 0; off >>= 1)
        cnt += __shfl_down_sync(0xFFFFFFFFu, cnt, off);
    if ((t & 31) == 0) atomicAdd(&s_sum, cnt);
    __syncthreads();

    int rank = s_sum;                        // placeholders before seq0
#pragma unroll
    for (int i = 0; i < RPB; i++) {
        if (ids[i] == PLACEHOLDER_ID) {
            int r = rank < (P - 1) ? rank : (P - 1);
            __stcs(out + (size_t)(r0 + i) * D4 + t, __ldg(&prompt[r * D4 + t]));
            rank++;
        }
    }
}

// ---------------------------------------------------------------------------
extern "C" void kernel_launch(void* const* d_in, const int* in_sizes, int n_in,
                              void* d_out, int out_size) {
    const int*    input_ids = (const int*)d_in[0];
    const float4* emb       = (const float4*)d_in[1];
    const float4* prompt    = (const float4*)d_in[2];
    float4*       out       = (float4*)d_out;

    fused_prompt_embed_kernel<<<GBLOCKS, GTPB>>>(input_ids, emb, prompt, out);
}